// round 15
// baseline (speedup 1.0000x reference)
#include <cuda_runtime.h>

// Windowed local attention, k=7, H=W=256, C=32, fp32.
// R7 structure (2 vertical px/thread, 8x7 union window, 98 accumulators,
// tile 32x8, 128 thr, grid 256) with channel-interleaved smem [g][pos][4]:
// one LDS.128 = 4 channels -> 4x fewer load latency events, same bytes.

#define H_IMG 256
#define W_IMG 256
#define C 32
#define K 7
#define PAD 3
#define TX 32
#define TY 8               // 2 rows per warp
#define HW 38              // TX + K - 1
#define HH 14              // TY + K - 1
#define NPOS (HW * HH)     // 532
#define NTHREADS 128
#define SMEM_BYTES (8 * NPOS * 16)   // 8 groups x 532 pos x float4 = 68096

// Stage one tensor's halo as float4 per (group, position), zero-pad OOB.
__device__ __forceinline__ void stage_halo(float4* __restrict__ buf,
                                           const float* __restrict__ src,
                                           int bx, int by, int tid) {
    #pragma unroll
    for (int g = 0; g < 8; g++) {
        for (int s = tid; s < NPOS; s += NTHREADS) {
            int hp = s / HW;
            int wp = s - hp * HW;
            int gw = bx * TX - PAD + wp;
            int gh = by * TY - PAD + hp;
            float4 r = make_float4(0.f, 0.f, 0.f, 0.f);
            if (gw >= 0 && gw < W_IMG && gh >= 0 && gh < H_IMG) {
                r = *reinterpret_cast<const float4*>(
                    src + ((gh << 8) + gw) * C + (g << 2));
            }
            buf[g * NPOS + s] = r;
        }
    }
}

__global__ __launch_bounds__(NTHREADS, 3)
void local_attn_kernel(const float* __restrict__ main_in,
                       const float* __restrict__ ref_in,
                       const float* __restrict__ val_in,
                       float* __restrict__ out) {
    extern __shared__ float4 smem4[];

    const int tid  = threadIdx.x;
    const int bx   = blockIdx.x, by = blockIdx.y;
    const int lane = tid & 31;           // px
    const int warp = tid >> 5;           // owns tile rows 2w, 2w+1
    const int h0   = warp << 1;
    const int s0   = h0 * HW + lane;     // window origin for pixel 0

    const int gy0   = by * TY + h0;
    const int gpix0 = ((gy0 << 8) + bx * TX + lane) * C;
    const int gpix1 = gpix0 + W_IMG * C;

    // ---- Stage ref halo ----
    stage_halo(smem4, ref_in, bx, by, tid);
    __syncthreads();

    // ---- Pass 1: scores for both pixels, group-outer, LDS.128 loads ----
    float sc0[K * K], sc1[K * K];
    #pragma unroll
    for (int p = 0; p < K * K; p++) { sc0[p] = 0.f; sc1[p] = 0.f; }

    #pragma unroll
    for (int g = 0; g < 8; g++) {
        float4 qp = *reinterpret_cast<const float4*>(main_in + gpix0 + (g << 2));
        float4 qs = *reinterpret_cast<const float4*>(main_in + gpix1 + (g << 2));
        const float4* bp = smem4 + g * NPOS + s0;
        #pragma unroll
        for (int dh = 0; dh < K + 1; dh++) {     // union: 8 rows
            #pragma unroll
            for (int dw = 0; dw < K; dw++) {
                float4 v = bp[dh * HW + dw];
                if (dh < K) {
                    float a = sc0[dh * K + dw];
                    a = fmaf(v.x, qp.x, a);
                    a = fmaf(v.y, qp.y, a);
                    a = fmaf(v.z, qp.z, a);
                    a = fmaf(v.w, qp.w, a);
                    sc0[dh * K + dw] = a;
                }
                if (dh >= 1) {
                    float b = sc1[(dh - 1) * K + dw];
                    b = fmaf(v.x, qs.x, b);
                    b = fmaf(v.y, qs.y, b);
                    b = fmaf(v.z, qs.z, b);
                    b = fmaf(v.w, qs.w, b);
                    sc1[(dh - 1) * K + dw] = b;
                }
            }
        }
    }

    // ---- Softmax (OOB positions carry score 0, included) ----
    {
        float mx0 = sc0[0], mx1 = sc1[0];
        #pragma unroll
        for (int p = 1; p < K * K; p++) { mx0 = fmaxf(mx0, sc0[p]); mx1 = fmaxf(mx1, sc1[p]); }
        float s0m = 0.f, s1m = 0.f;
        #pragma unroll
        for (int p = 0; p < K * K; p++) {
            sc0[p] = __expf(sc0[p] - mx0); s0m += sc0[p];
            sc1[p] = __expf(sc1[p] - mx1); s1m += sc1[p];
        }
        float i0 = 1.f / s0m, i1 = 1.f / s1m;
        #pragma unroll
        for (int p = 0; p < K * K; p++) { sc0[p] *= i0; sc1[p] *= i1; }
    }

    // ---- Stage val halo (reuse buffer) ----
    __syncthreads();
    stage_halo(smem4, val_in, bx, by, tid);
    __syncthreads();

    // ---- Pass 2: outputs for both pixels, group-outer, LDS.128 loads ----
    #pragma unroll
    for (int g = 0; g < 8; g++) {
        const float4* bp = smem4 + g * NPOS + s0;
        float4 a0 = make_float4(0.f, 0.f, 0.f, 0.f);
        float4 a1 = make_float4(0.f, 0.f, 0.f, 0.f);
        #pragma unroll
        for (int dh = 0; dh < K + 1; dh++) {
            #pragma unroll
            for (int dw = 0; dw < K; dw++) {
                float4 v = bp[dh * HW + dw];
                if (dh < K) {
                    float w0 = sc0[dh * K + dw];
                    a0.x = fmaf(v.x, w0, a0.x);
                    a0.y = fmaf(v.y, w0, a0.y);
                    a0.z = fmaf(v.z, w0, a0.z);
                    a0.w = fmaf(v.w, w0, a0.w);
                }
                if (dh >= 1) {
                    float w1 = sc1[(dh - 1) * K + dw];
                    a1.x = fmaf(v.x, w1, a1.x);
                    a1.y = fmaf(v.y, w1, a1.y);
                    a1.z = fmaf(v.z, w1, a1.z);
                    a1.w = fmaf(v.w, w1, a1.w);
                }
            }
        }
        *reinterpret_cast<float4*>(out + gpix0 + (g << 2)) = a0;
        *reinterpret_cast<float4*>(out + gpix1 + (g << 2)) = a1;
    }
}

extern "C" void kernel_launch(void* const* d_in, const int* in_sizes, int n_in,
                              void* d_out, int out_size) {
    const float* main_in = (const float*)d_in[0];
    const float* ref_in  = (const float*)d_in[1];
    const float* val_in  = (const float*)d_in[2];
    float* out = (float*)d_out;

    cudaFuncSetAttribute(local_attn_kernel,
                         cudaFuncAttributeMaxDynamicSharedMemorySize, SMEM_BYTES);

    dim3 grid(W_IMG / TX, H_IMG / TY);
    local_attn_kernel<<<grid, NTHREADS, SMEM_BYTES>>>(main_in, ref_in, val_in, out);
}

// round 16
// speedup vs baseline: 1.0486x; 1.0486x over previous
#include <cuda_runtime.h>
#include <cuda_fp16.h>

// Windowed local attention, k=7, H=W=256, C=32, fp32 in/out.
// R7 structure verbatim (2 vertical px/thread, 8x7 union window, 98 accs,
// tile 32x8, 128 thr, grid 256, single reused halo buffer) with ONE change:
// the val halo is stored as half2 channel-pairs -> pass-2 crossbar bytes
// halved (total 470 -> 352 MB). Scores/accumulation stay fp32.

#define H_IMG 256
#define W_IMG 256
#define C 32
#define K 7
#define PAD 3
#define TX 32
#define TY 8               // 2 rows per warp
#define HW 38              // TX + K - 1
#define HH 14              // TY + K - 1
#define NPOS (HW * HH)     // 532
#define CS 533             // fp32 ref: channel stride (odd -> conflict-free)
#define NTHREADS 128
#define SMEM_BYTES (C * CS * 4)   // 68224 (val fp16 needs only 34KB of it)

// Stage ref halo: [c][pos] channel-major fp32, zero-padded OOB. (R7 verbatim)
__device__ __forceinline__ void stage_halo_f32(float* __restrict__ buf,
                                               const float* __restrict__ src,
                                               int bx, int by, int tid) {
    for (int idx = tid; idx < NPOS * (C / 4); idx += NTHREADS) {
        int g  = idx & 7;
        int s  = idx >> 3;
        int wp = s % HW;
        int hp = s / HW;
        int gw = bx * TX - PAD + wp;
        int gh = by * TY - PAD + hp;
        float4 r = make_float4(0.f, 0.f, 0.f, 0.f);
        if (gw >= 0 && gw < W_IMG && gh >= 0 && gh < H_IMG) {
            r = *reinterpret_cast<const float4*>(src + ((gh << 8) + gw) * C + (g << 2));
        }
        int c0 = g << 2;
        buf[(c0 + 0) * CS + s] = r.x;
        buf[(c0 + 1) * CS + s] = r.y;
        buf[(c0 + 2) * CS + s] = r.z;
        buf[(c0 + 3) * CS + s] = r.w;
    }
}

// Stage val halo: [pair=c/2][pos] as half2, zero-padded OOB.
__device__ __forceinline__ void stage_halo_f16(__half2* __restrict__ buf,
                                               const float* __restrict__ src,
                                               int bx, int by, int tid) {
    for (int idx = tid; idx < NPOS * (C / 4); idx += NTHREADS) {
        int g  = idx & 7;                  // 4-channel group
        int s  = idx >> 3;
        int wp = s % HW;
        int hp = s / HW;
        int gw = bx * TX - PAD + wp;
        int gh = by * TY - PAD + hp;
        float4 r = make_float4(0.f, 0.f, 0.f, 0.f);
        if (gw >= 0 && gw < W_IMG && gh >= 0 && gh < H_IMG) {
            r = *reinterpret_cast<const float4*>(src + ((gh << 8) + gw) * C + (g << 2));
        }
        buf[(2 * g + 0) * NPOS + s] = __floats2half2_rn(r.x, r.y);
        buf[(2 * g + 1) * NPOS + s] = __floats2half2_rn(r.z, r.w);
    }
}

__global__ __launch_bounds__(NTHREADS, 3)
void local_attn_kernel(const float* __restrict__ main_in,
                       const float* __restrict__ ref_in,
                       const float* __restrict__ val_in,
                       float* __restrict__ out) {
    extern __shared__ float smem[];
    float*   bufR = smem;
    __half2* bufV = reinterpret_cast<__half2*>(smem);

    const int tid  = threadIdx.x;
    const int bx   = blockIdx.x, by = blockIdx.y;
    const int lane = tid & 31;           // px
    const int warp = tid >> 5;           // owns tile rows 2w, 2w+1
    const int h0   = warp << 1;
    const int s0   = h0 * HW + lane;     // window origin for pixel 0

    const int gy0   = by * TY + h0;
    const int gpix0 = ((gy0 << 8) + bx * TX + lane) * C;
    const int gpix1 = gpix0 + W_IMG * C;

    // ---- Stage ref halo (fp32) ----
    stage_halo_f32(bufR, ref_in, bx, by, tid);
    __syncthreads();

    // ---- Pass 1: scores for both pixels, 2 chunks of 16 channels (R7) ----
    float sc0[K * K], sc1[K * K];
    #pragma unroll
    for (int p = 0; p < K * K; p++) { sc0[p] = 0.f; sc1[p] = 0.f; }

    #pragma unroll
    for (int cc = 0; cc < 2; cc++) {
        float q0[16], q1[16];
        #pragma unroll
        for (int i = 0; i < 4; i++) {
            float4 a = *reinterpret_cast<const float4*>(main_in + gpix0 + cc * 16 + 4 * i);
            float4 b = *reinterpret_cast<const float4*>(main_in + gpix1 + cc * 16 + 4 * i);
            q0[4 * i + 0] = a.x; q0[4 * i + 1] = a.y; q0[4 * i + 2] = a.z; q0[4 * i + 3] = a.w;
            q1[4 * i + 0] = b.x; q1[4 * i + 1] = b.y; q1[4 * i + 2] = b.z; q1[4 * i + 3] = b.w;
        }
        #pragma unroll
        for (int c = 0; c < 16; c++) {
            const float* base = bufR + (cc * 16 + c) * CS + s0;
            #pragma unroll
            for (int dh = 0; dh < K + 1; dh++) {     // union: 8 rows
                #pragma unroll
                for (int dw = 0; dw < K; dw++) {
                    float v = base[dh * HW + dw];
                    if (dh < K)  sc0[dh * K + dw]       = fmaf(v, q0[c], sc0[dh * K + dw]);
                    if (dh >= 1) sc1[(dh - 1) * K + dw] = fmaf(v, q1[c], sc1[(dh - 1) * K + dw]);
                }
            }
        }
    }

    // ---- Softmax (OOB positions carry score 0, included) ----
    {
        float mx0 = sc0[0], mx1 = sc1[0];
        #pragma unroll
        for (int p = 1; p < K * K; p++) { mx0 = fmaxf(mx0, sc0[p]); mx1 = fmaxf(mx1, sc1[p]); }
        float s0m = 0.f, s1m = 0.f;
        #pragma unroll
        for (int p = 0; p < K * K; p++) {
            sc0[p] = __expf(sc0[p] - mx0); s0m += sc0[p];
            sc1[p] = __expf(sc1[p] - mx1); s1m += sc1[p];
        }
        float i0 = 1.f / s0m, i1 = 1.f / s1m;
        #pragma unroll
        for (int p = 0; p < K * K; p++) { sc0[p] *= i0; sc1[p] *= i1; }
    }

    // ---- Stage val halo (fp16, reuse buffer) ----
    __syncthreads();
    stage_halo_f16(bufV, val_in, bx, by, tid);
    __syncthreads();

    // ---- Pass 2: outputs for both pixels, 4-channel groups, half2 loads ----
    #pragma unroll
    for (int g = 0; g < 8; g++) {
        float4 a0 = make_float4(0.f, 0.f, 0.f, 0.f);
        float4 a1 = make_float4(0.f, 0.f, 0.f, 0.f);
        const __half2* bpA = bufV + (2 * g + 0) * NPOS + s0;   // ch 4g, 4g+1
        const __half2* bpB = bufV + (2 * g + 1) * NPOS + s0;   // ch 4g+2, 4g+3
        #pragma unroll
        for (int dh = 0; dh < K + 1; dh++) {
            #pragma unroll
            for (int dw = 0; dw < K; dw++) {
                float2 vA = __half22float2(bpA[dh * HW + dw]);
                float2 vB = __half22float2(bpB[dh * HW + dw]);
                if (dh < K) {
                    float w0 = sc0[dh * K + dw];
                    a0.x = fmaf(vA.x, w0, a0.x);
                    a0.y = fmaf(vA.y, w0, a0.y);
                    a0.z = fmaf(vB.x, w0, a0.z);
                    a0.w = fmaf(vB.y, w0, a0.w);
                }
                if (dh >= 1) {
                    float w1 = sc1[(dh - 1) * K + dw];
                    a1.x = fmaf(vA.x, w1, a1.x);
                    a1.y = fmaf(vA.y, w1, a1.y);
                    a1.z = fmaf(vB.x, w1, a1.z);
                    a1.w = fmaf(vB.y, w1, a1.w);
                }
            }
        }
        *reinterpret_cast<float4*>(out + gpix0 + (g << 2)) = a0;
        *reinterpret_cast<float4*>(out + gpix1 + (g << 2)) = a1;
    }
}

extern "C" void kernel_launch(void* const* d_in, const int* in_sizes, int n_in,
                              void* d_out, int out_size) {
    const float* main_in = (const float*)d_in[0];
    const float* ref_in  = (const float*)d_in[1];
    const float* val_in  = (const float*)d_in[2];
    float* out = (float*)d_out;

    cudaFuncSetAttribute(local_attn_kernel,
                         cudaFuncAttributeMaxDynamicSharedMemorySize, SMEM_BYTES);

    dim3 grid(W_IMG / TX, H_IMG / TY);
    local_attn_kernel<<<grid, NTHREADS, SMEM_BYTES>>>(main_in, ref_in, val_in, out);
}